// round 5
// baseline (speedup 1.0000x reference)
#include <cuda_runtime.h>
#include <cuda_fp16.h>
#include <cuda_fp8.h>
#include <math.h>
#include <stdint.h>

#define NP 8192
#define MP 8192
#define DIMS 32
#define EPSV 10.0f
#define THRESH2 (1e-5f * 1e-5f)
#define MAX_ITER 50
#define FP8_ITERS 42 /* then 8 fp16 polish iterations */
#define SCALE_F 65536.0f
#define INV_SCALE_F (1.0f / 65536.0f)
#define LOG_SCALE_F 11.090354888959125f /* ln(65536) */
#define S8_F 256.0f
#define CS 16
#define CHUNK (MP / CS) /* 512 */
#define RPB 32
#define NRB (NP / RPB) /* 256 row-groups */

// fp16 K (scaled 2^16) row-major + transposed (finalize + polish matvecs);
// fp8 K (scaled 2^8) row-major + transposed (fast matvecs). 384MB scratch.
__device__ __half   g_K1[(size_t)NP * MP];
__device__ __half   g_K1T[(size_t)NP * MP];
__device__ uint8_t  g_K8[(size_t)NP * MP];
__device__ uint8_t  g_K8T[(size_t)NP * MP];
__device__ float g_a[NP];
__device__ float g_b[MP];
__device__ float g_pa[CS * NP]; // partials of K @ b    (layout [cs][row])
__device__ float g_pb[CS * MP]; // partials of K^T @ a  (layout [cs][row])
__device__ float g_errp[NRB];
__device__ int   g_cntA[NRB];
__device__ int   g_cntB[NRB];
__device__ int   g_cnt2;
__device__ int   g_done;
__device__ float g_part[16384];

// ---------------------------------------------------------------------------
__global__ void sink_init()
{
    int i = blockIdx.x * 256 + threadIdx.x;
    if (i < MP) g_b[i] = 1.0f;
    if (i < NRB) { g_cntA[i] = 0; g_cntB[i] = 0; }
    if (i == 0) { g_done = 0; g_cnt2 = 0; }
}

// ---------------------------------------------------------------------------
// Build: e = exp(-max(C,0)/EPS). Store e*2^16 as fp16 (K1 + K1T) and e*2^8
// as fp8 e4m3 (K8 + K8T). 64x64 tile per block.
__global__ __launch_bounds__(256) void build_K(const float* __restrict__ x,
                                               const float* __restrict__ y)
{
    __shared__ float sx[64][DIMS + 1];
    __shared__ float sy[64][DIMS + 1];
    __shared__ float sx2[64];
    __shared__ float sy2[64];
    __shared__ __half  stile[64][65];
    __shared__ uint8_t s8tile[64][68];

    const int tid = threadIdx.x;
    const int I0 = blockIdx.y * 64;
    const int J0 = blockIdx.x * 64;

    for (int idx = tid; idx < 64 * DIMS; idx += 256) {
        int r = idx >> 5, k = idx & 31;
        sx[r][k] = x[(I0 + r) * DIMS + k];
        sy[r][k] = y[(J0 + r) * DIMS + k];
    }
    __syncthreads();
    if (tid < 64) {
        float s = 0.f;
        #pragma unroll
        for (int k = 0; k < DIMS; k++) { float v = sx[tid][k]; s = fmaf(v, v, s); }
        sx2[tid] = s;
    } else if (tid < 128) {
        int r = tid - 64;
        float s = 0.f;
        #pragma unroll
        for (int k = 0; k < DIMS; k++) { float v = sy[r][k]; s = fmaf(v, v, s); }
        sy2[r] = s;
    }
    __syncthreads();

    const int ty = tid >> 4, tx = tid & 15;
    const int r0 = ty * 4, c0 = tx * 4;
    float acc[4][4];
    #pragma unroll
    for (int i = 0; i < 4; i++)
        #pragma unroll
        for (int j = 0; j < 4; j++) acc[i][j] = 0.f;

    #pragma unroll
    for (int k = 0; k < DIMS; k++) {
        float a0 = sx[r0 + 0][k], a1 = sx[r0 + 1][k];
        float a2 = sx[r0 + 2][k], a3 = sx[r0 + 3][k];
        float b0 = sy[c0 + 0][k], b1 = sy[c0 + 1][k];
        float b2 = sy[c0 + 2][k], b3 = sy[c0 + 3][k];
        acc[0][0] = fmaf(a0, b0, acc[0][0]); acc[0][1] = fmaf(a0, b1, acc[0][1]);
        acc[0][2] = fmaf(a0, b2, acc[0][2]); acc[0][3] = fmaf(a0, b3, acc[0][3]);
        acc[1][0] = fmaf(a1, b0, acc[1][0]); acc[1][1] = fmaf(a1, b1, acc[1][1]);
        acc[1][2] = fmaf(a1, b2, acc[1][2]); acc[1][3] = fmaf(a1, b3, acc[1][3]);
        acc[2][0] = fmaf(a2, b0, acc[2][0]); acc[2][1] = fmaf(a2, b1, acc[2][1]);
        acc[2][2] = fmaf(a2, b2, acc[2][2]); acc[2][3] = fmaf(a2, b3, acc[2][3]);
        acc[3][0] = fmaf(a3, b0, acc[3][0]); acc[3][1] = fmaf(a3, b1, acc[3][1]);
        acc[3][2] = fmaf(a3, b2, acc[3][2]); acc[3][3] = fmaf(a3, b3, acc[3][3]);
    }

    #pragma unroll
    for (int i = 0; i < 4; i++) {
        #pragma unroll
        for (int j = 0; j < 4; j++) {
            float C = sx2[r0 + i] + sy2[c0 + j] - 2.f * acc[i][j];
            C = fmaxf(C, 0.f);
            float e16 = exp2f(fmaf(C, -0.14426950408889634f, 16.0f));
            stile[r0 + i][c0 + j] = __float2half_rn(fminf(e16, 65504.f));
            s8tile[r0 + i][c0 + j] = (uint8_t)__nv_cvt_float_to_fp8(
                e16 * 0.00390625f, __NV_SATFINITE, __NV_E4M3);
        }
    }
    __syncthreads();

    for (int idx = tid; idx < 4096; idx += 256) {
        int r = idx >> 6, c = idx & 63;
        g_K1[(size_t)(I0 + r) * MP + (J0 + c)] = stile[r][c];
        g_K1T[(size_t)(J0 + r) * NP + (I0 + c)] = stile[c][r];
    }
    for (int idx = tid; idx < 1024; idx += 256) {
        int r = idx >> 4, c4 = (idx & 15) * 4;
        uchar4 v;
        v.x = s8tile[r][c4 + 0]; v.y = s8tile[r][c4 + 1];
        v.z = s8tile[r][c4 + 2]; v.w = s8tile[r][c4 + 3];
        *(uchar4*)(g_K8 + (size_t)(I0 + r) * MP + (J0 + c4)) = v;
        uchar4 t;
        t.x = s8tile[c4 + 0][r]; t.y = s8tile[c4 + 1][r];
        t.z = s8tile[c4 + 2][r]; t.w = s8tile[c4 + 3][r];
        *(uchar4*)(g_K8T + (size_t)(J0 + r) * NP + (I0 + c4)) = t;
    }
}

// ---------------------------------------------------------------------------
// Fused epilogue: last block per 32-row group combines the CS partials into
// the output vector (deterministic fixed-order sum). For the b-pass it also
// computes the err^2 partial, and the last combiner overall sets g_done.
__device__ __forceinline__ void epilogue_combine(
    float* __restrict__ part, float* __restrict__ vecout,
    const float* __restrict__ mul, float scale, int* __restrict__ cnt,
    int rb, int lane, int compute_err)
{
    __threadfence();
    __shared__ int s_last;
    if (threadIdx.x == 0)
        s_last = (atomicAdd(&cnt[rb], 1) == CS - 1);
    __syncthreads();
    if (!s_last) return;
    if (threadIdx.x == 0) cnt[rb] = 0;
    __threadfence();

    if (threadIdx.x < 32) {
        const int row = rb * RPB + lane;
        float s = 0.f;
        #pragma unroll
        for (int c = 0; c < CS; c++) s += part[c * NP + row];
        float nv = __fdividef(mul[row] * scale, s);
        if (compute_err) {
            float d = nv - vecout[row];
            vecout[row] = nv;
            float e = d * d;
            #pragma unroll
            for (int o = 16; o; o >>= 1) e += __shfl_xor_sync(0xffffffffu, e, o);
            if (lane == 0) g_errp[rb] = e;
        } else {
            vecout[row] = nv;
        }
    }

    if (compute_err) {
        __threadfence();
        __shared__ int s_last2;
        if (threadIdx.x == 0)
            s_last2 = (atomicAdd(&g_cnt2, 1) == NRB - 1);
        __syncthreads();
        if (s_last2 && threadIdx.x < 32) {
            if (threadIdx.x == 0) g_cnt2 = 0;
            __threadfence();
            float s = 0.f;
            #pragma unroll
            for (int i = 0; i < NRB / 32; i++) s += g_errp[i * 32 + lane];
            #pragma unroll
            for (int o = 16; o; o >>= 1) s += __shfl_xor_sync(0xffffffffu, s, o);
            if (lane == 0 && s < THRESH2) g_done = 1;
        }
    }
}

// ---------------------------------------------------------------------------
// fp8 GEMV with fused combine. Tile = 32 rows x 512 cols per block.
#define W_FMA(wrd, bf4, acc)                                                   \
    {                                                                          \
        __half2_raw lo_ = __nv_cvt_fp8x2_to_halfraw2(                          \
            (__nv_fp8x2_storage_t)((wrd) & 0xffffu), __NV_E4M3);               \
        __half2_raw hi_ = __nv_cvt_fp8x2_to_halfraw2(                          \
            (__nv_fp8x2_storage_t)((wrd) >> 16), __NV_E4M3);                   \
        float2 fl_ = __half22float2(*(__half2*)&lo_);                          \
        float2 fh_ = __half22float2(*(__half2*)&hi_);                          \
        acc = fmaf(fl_.x, (bf4).x, acc); acc = fmaf(fl_.y, (bf4).y, acc);      \
        acc = fmaf(fh_.x, (bf4).z, acc); acc = fmaf(fh_.y, (bf4).w, acc);      \
    }

#define ROW16(v, acc)                                                          \
    { W_FMA((v).x, b0, acc); W_FMA((v).y, b1, acc);                            \
      W_FMA((v).z, b2, acc); W_FMA((v).w, b3, acc); }

__global__ __launch_bounds__(256) void sink_matvec8(
    const uint8_t* __restrict__ K8, const float* __restrict__ vin,
    float* __restrict__ part_out, float* __restrict__ vecout,
    const float* __restrict__ mul, float scale, int* __restrict__ cnt,
    int compute_err)
{
    if (g_done) return;
    const int cs = blockIdx.x & (CS - 1);
    const int rb = blockIdx.x / CS;
    const int warp = threadIdx.x >> 5;
    const int lane = threadIdx.x & 31;
    const int rbase = rb * RPB + warp * 4;
    const int col0 = cs * CHUNK + lane * 16;

    const float4* bv = (const float4*)(vin + col0);
    float4 b0 = bv[0], b1 = bv[1], b2 = bv[2], b3 = bv[3];

    const size_t base = (size_t)rbase * MP + col0;
    uint4 v0 = __ldcg((const uint4*)(K8 + base));
    uint4 v1 = __ldcg((const uint4*)(K8 + base + MP));
    uint4 v2 = __ldcg((const uint4*)(K8 + base + 2 * MP));
    uint4 v3 = __ldcg((const uint4*)(K8 + base + 3 * MP));

    float a0 = 0.f, a1 = 0.f, a2 = 0.f, a3 = 0.f;
    ROW16(v0, a0);
    ROW16(v1, a1);
    ROW16(v2, a2);
    ROW16(v3, a3);

    #pragma unroll
    for (int o = 16; o; o >>= 1) {
        a0 += __shfl_xor_sync(0xffffffffu, a0, o);
        a1 += __shfl_xor_sync(0xffffffffu, a1, o);
        a2 += __shfl_xor_sync(0xffffffffu, a2, o);
        a3 += __shfl_xor_sync(0xffffffffu, a3, o);
    }
    if (lane == 0)
        *(float4*)(part_out + (size_t)cs * NP + rbase) =
            make_float4(a0, a1, a2, a3);

    epilogue_combine(part_out, vecout, mul, scale, cnt, rb, lane, compute_err);
}

// ---------------------------------------------------------------------------
// fp16 GEMV with fused combine (polish phase).
#define HQ_FMA(u, bA, bB, acc)                                                 \
    {                                                                          \
        float2 f0_ = __half22float2(*reinterpret_cast<__half2*>(&(u).x));      \
        float2 f1_ = __half22float2(*reinterpret_cast<__half2*>(&(u).y));      \
        float2 f2_ = __half22float2(*reinterpret_cast<__half2*>(&(u).z));      \
        float2 f3_ = __half22float2(*reinterpret_cast<__half2*>(&(u).w));      \
        acc = fmaf(f0_.x, (bA).x, acc); acc = fmaf(f0_.y, (bA).y, acc);        \
        acc = fmaf(f1_.x, (bA).z, acc); acc = fmaf(f1_.y, (bA).w, acc);        \
        acc = fmaf(f2_.x, (bB).x, acc); acc = fmaf(f2_.y, (bB).y, acc);        \
        acc = fmaf(f3_.x, (bB).z, acc); acc = fmaf(f3_.y, (bB).w, acc);        \
    }

__global__ __launch_bounds__(256) void sink_matvec16(
    const __half* __restrict__ K, const float* __restrict__ vin,
    float* __restrict__ part_out, float* __restrict__ vecout,
    const float* __restrict__ mul, float scale, int* __restrict__ cnt,
    int compute_err)
{
    if (g_done) return;
    const int cs = blockIdx.x & (CS - 1);
    const int rb = blockIdx.x / CS;
    const int warp = threadIdx.x >> 5;
    const int lane = threadIdx.x & 31;
    const int rbase = rb * RPB + warp * 4;
    const int col0 = cs * CHUNK + lane * 16;

    const float4* bv = (const float4*)(vin + col0);
    float4 b0 = bv[0], b1 = bv[1], b2 = bv[2], b3 = bv[3];

    const __half* kr = K + (size_t)rbase * MP + col0;
    float a0 = 0.f, a1 = 0.f, a2 = 0.f, a3 = 0.f;
    {
        uint4 u0 = __ldcg((const uint4*)kr);
        uint4 u1 = __ldcg((const uint4*)kr + 1);
        HQ_FMA(u0, b0, b1, a0); HQ_FMA(u1, b2, b3, a0);
    }
    {
        uint4 u0 = __ldcg((const uint4*)(kr + MP));
        uint4 u1 = __ldcg((const uint4*)(kr + MP) + 1);
        HQ_FMA(u0, b0, b1, a1); HQ_FMA(u1, b2, b3, a1);
    }
    {
        uint4 u0 = __ldcg((const uint4*)(kr + 2 * MP));
        uint4 u1 = __ldcg((const uint4*)(kr + 2 * MP) + 1);
        HQ_FMA(u0, b0, b1, a2); HQ_FMA(u1, b2, b3, a2);
    }
    {
        uint4 u0 = __ldcg((const uint4*)(kr + 3 * MP));
        uint4 u1 = __ldcg((const uint4*)(kr + 3 * MP) + 1);
        HQ_FMA(u0, b0, b1, a3); HQ_FMA(u1, b2, b3, a3);
    }

    #pragma unroll
    for (int o = 16; o; o >>= 1) {
        a0 += __shfl_xor_sync(0xffffffffu, a0, o);
        a1 += __shfl_xor_sync(0xffffffffu, a1, o);
        a2 += __shfl_xor_sync(0xffffffffu, a2, o);
        a3 += __shfl_xor_sync(0xffffffffu, a3, o);
    }
    if (lane == 0)
        *(float4*)(part_out + (size_t)cs * NP + rbase) =
            make_float4(a0, a1, a2, a3);

    epilogue_combine(part_out, vecout, mul, scale, cnt, rb, lane, compute_err);
}

// ---------------------------------------------------------------------------
// T = a * (K1/2^16) * b; cost term = T * C with C = EPS*(ln 2^16 - ln K1).
__global__ __launch_bounds__(256) void finalize_T(float* __restrict__ Tout,
                                                  int write_T)
{
    const size_t e0 = ((size_t)blockIdx.x * 4096) + (size_t)threadIdx.x * 16;
    const int i = (int)(e0 >> 13);
    const float ai = g_a[i] * INV_SCALE_F;
    float cs = 0.f;

    #pragma unroll
    for (int g = 0; g < 4; ++g) {
        const size_t e = e0 + g * 4;
        const int j = (int)(e & 8191);
        uint2 kv2 = *reinterpret_cast<const uint2*>(g_K1 + e);
        __half2 h0 = *reinterpret_cast<__half2*>(&kv2.x);
        __half2 h1 = *reinterpret_cast<__half2*>(&kv2.y);
        float2 f0 = __half22float2(h0);
        float2 f1 = __half22float2(h1);
        const float4 bv = *reinterpret_cast<const float4*>(g_b + j);

        float t0 = ai * f0.x * bv.x;
        float t1 = ai * f0.y * bv.y;
        float t2 = ai * f1.x * bv.z;
        float t3 = ai * f1.y * bv.w;

        if (f0.x > 0.f) cs = fmaf(t0, EPSV * (LOG_SCALE_F - __logf(f0.x)), cs);
        if (f0.y > 0.f) cs = fmaf(t1, EPSV * (LOG_SCALE_F - __logf(f0.y)), cs);
        if (f1.x > 0.f) cs = fmaf(t2, EPSV * (LOG_SCALE_F - __logf(f1.x)), cs);
        if (f1.y > 0.f) cs = fmaf(t3, EPSV * (LOG_SCALE_F - __logf(f1.y)), cs);

        if (write_T) {
            if ((((uintptr_t)Tout) & 15) == 0) {
                *reinterpret_cast<float4*>(Tout + e) = make_float4(t0, t1, t2, t3);
            } else {
                Tout[e + 0] = t0;
                Tout[e + 1] = t1;
                Tout[e + 2] = t2;
                Tout[e + 3] = t3;
            }
        }
    }

    __shared__ float sd[256];
    sd[threadIdx.x] = cs;
    __syncthreads();
    for (int o = 128; o; o >>= 1) {
        if (threadIdx.x < o) sd[threadIdx.x] += sd[threadIdx.x + o];
        __syncthreads();
    }
    if (threadIdx.x == 0) g_part[blockIdx.x] = sd[0];
}

__global__ __launch_bounds__(256) void reduce_cost(float* __restrict__ cost_out)
{
    __shared__ double sd[256];
    double s = 0.0;
    for (int i = threadIdx.x; i < 16384; i += 256) s += (double)g_part[i];
    sd[threadIdx.x] = s;
    __syncthreads();
    for (int o = 128; o; o >>= 1) {
        if (threadIdx.x < o) sd[threadIdx.x] += sd[threadIdx.x + o];
        __syncthreads();
    }
    if (threadIdx.x == 0) cost_out[0] = (float)sd[0];
}

// ---------------------------------------------------------------------------
extern "C" void kernel_launch(void* const* d_in, const int* in_sizes, int n_in,
                              void* d_out, int out_size)
{
    const float* x = (const float*)d_in[0];
    const float* y = (const float*)d_in[1];
    const float* p = (const float*)d_in[2];
    const float* q = (const float*)d_in[3];
    float* out = (float*)d_out;

    void *k1p, *k1tp, *k8p, *k8tp, *ap, *bp, *pap, *pbp, *cap, *cbp;
    cudaGetSymbolAddress(&k1p, g_K1);
    cudaGetSymbolAddress(&k1tp, g_K1T);
    cudaGetSymbolAddress(&k8p, g_K8);
    cudaGetSymbolAddress(&k8tp, g_K8T);
    cudaGetSymbolAddress(&ap, g_a);
    cudaGetSymbolAddress(&bp, g_b);
    cudaGetSymbolAddress(&pap, g_pa);
    cudaGetSymbolAddress(&pbp, g_pb);
    cudaGetSymbolAddress(&cap, g_cntA);
    cudaGetSymbolAddress(&cbp, g_cntB);

    sink_init<<<32, 256>>>();
    dim3 bgrid(MP / 64, NP / 64);
    build_K<<<bgrid, 256>>>(x, y);

    const int mv_grid = (NP / RPB) * CS; // 4096
    for (int it = 0; it < MAX_ITER; ++it) {
        if (it < FP8_ITERS) {
            sink_matvec8<<<mv_grid, 256>>>((const uint8_t*)k8p,
                                           (const float*)bp, (float*)pap,
                                           (float*)ap, p, S8_F, (int*)cap, 0);
            sink_matvec8<<<mv_grid, 256>>>((const uint8_t*)k8tp,
                                           (const float*)ap, (float*)pbp,
                                           (float*)bp, q, S8_F, (int*)cbp, 1);
        } else {
            sink_matvec16<<<mv_grid, 256>>>((const __half*)k1p,
                                            (const float*)bp, (float*)pap,
                                            (float*)ap, p, SCALE_F,
                                            (int*)cap, 0);
            sink_matvec16<<<mv_grid, 256>>>((const __half*)k1tp,
                                            (const float*)ap, (float*)pbp,
                                            (float*)bp, q, SCALE_F,
                                            (int*)cbp, 1);
        }
    }

    const long long total = (long long)NP * MP;
    if ((long long)out_size == total + 1) {
        finalize_T<<<16384, 256>>>(out + 1, 1);
        reduce_cost<<<1, 256>>>(out);
    } else if ((long long)out_size == total) {
        finalize_T<<<16384, 256>>>(out, 1);
    } else if ((long long)out_size > total) {
        finalize_T<<<16384, 256>>>(out + (out_size - total), 1);
        reduce_cost<<<1, 256>>>(out);
    } else {
        finalize_T<<<16384, 256>>>(nullptr, 0);
        reduce_cost<<<1, 256>>>(out);
    }
}